// round 8
// baseline (speedup 1.0000x reference)
#include <cuda_runtime.h>
#include <math_constants.h>
#include <stdint.h>

// GlobalAttentionPooling, fused single-kernel version.
// out[g,:] = sum_{i in seg g} softmax_g(x_i . W + b) * x_i
// N=100000, D=512, G=256. batch SORTED -> contiguous segments.
//
// - batch dtype (int32 vs int64) detected on device (JAX x64-off downcast).
// - One-pass streaming online-softmax; 2 rows per warp iteration for MLP=8.
// - Grid = G*SPLIT blocks; last block per graph (atomic counter) merges the
//   SPLIT partials and writes the output row. Counter reset by finisher so
//   the kernel is graph-replay deterministic.

#define D_DIM  512
#define G_NUM  256
#define SPLIT  4
#define WPB    8
#define T_P1   (WPB * 32)
#define NPART  (G_NUM * SPLIT)
#define RSTRIDE (SPLIT * WPB)      // row stride between a warp's consecutive rows

__device__ __align__(16) float g_part_m[NPART];
__device__ __align__(16) float g_part_s[NPART];
__device__ __align__(16) float g_part_acc[(size_t)NPART * D_DIM];
__device__ int g_cnt[G_NUM];       // zero-initialized at module load; finisher resets

__device__ __forceinline__ int lower_bound_batch(const int* __restrict__ a32,
                                                 int n, int v, int stride) {
    int lo = 0, hi = n;
    while (lo < hi) {
        int mid = (lo + hi) >> 1;
        if (a32[mid * stride] < v) lo = mid + 1; else hi = mid;
    }
    return lo;
}

// tree-reduced 16-element partial dot (per lane)
#define ROW_DOT(res, v0, v1, v2, v3, w0, w1, w2, w3)                          \
    do {                                                                      \
        float da = v0.x * w0.x; da = fmaf(v0.y, w0.y, da);                    \
        da = fmaf(v0.z, w0.z, da); da = fmaf(v0.w, w0.w, da);                 \
        float db = v1.x * w1.x; db = fmaf(v1.y, w1.y, db);                    \
        db = fmaf(v1.z, w1.z, db); db = fmaf(v1.w, w1.w, db);                 \
        float dc = v2.x * w2.x; dc = fmaf(v2.y, w2.y, dc);                    \
        dc = fmaf(v2.z, w2.z, dc); dc = fmaf(v2.w, w2.w, dc);                 \
        float dd = v3.x * w3.x; dd = fmaf(v3.y, w3.y, dd);                    \
        dd = fmaf(v3.z, w3.z, dd); dd = fmaf(v3.w, w3.w, dd);                 \
        res = (da + db) + (dc + dd);                                          \
    } while (0)

#define AXPY4(acc, p, v)                                                      \
    acc.x = fmaf(p, v.x, acc.x); acc.y = fmaf(p, v.y, acc.y);                 \
    acc.z = fmaf(p, v.z, acc.z); acc.w = fmaf(p, v.w, acc.w);

#define SCALE_AXPY4(acc, c, p, v)                                             \
    acc.x = fmaf(acc.x, c, p * v.x); acc.y = fmaf(acc.y, c, p * v.y);         \
    acc.z = fmaf(acc.z, c, p * v.z); acc.w = fmaf(acc.w, c, p * v.w);

// acc = acc + p1*u + p2*v
#define AXPY2_4(acc, p1, u, p2, v)                                            \
    acc.x = fmaf(p1, u.x, fmaf(p2, v.x, acc.x));                              \
    acc.y = fmaf(p1, u.y, fmaf(p2, v.y, acc.y));                              \
    acc.z = fmaf(p1, u.z, fmaf(p2, v.z, acc.z));                              \
    acc.w = fmaf(p1, u.w, fmaf(p2, v.w, acc.w));

// acc = acc*c + p1*u + p2*v
#define SCALE_AXPY2_4(acc, c, p1, u, p2, v)                                   \
    acc.x = fmaf(acc.x, c, fmaf(p1, u.x, p2 * v.x));                          \
    acc.y = fmaf(acc.y, c, fmaf(p1, u.y, p2 * v.y));                          \
    acc.z = fmaf(acc.z, c, fmaf(p1, u.z, p2 * v.z));                          \
    acc.w = fmaf(acc.w, c, fmaf(p1, u.w, p2 * v.w));

template <bool VEC>
__global__ __launch_bounds__(T_P1, 2)
void gap_fused(const float* __restrict__ x,
               const float* __restrict__ Wv,
               const float* __restrict__ bv,
               const int* __restrict__ batch32,
               int N,
               float* __restrict__ out)
{
    __shared__ int   sb[2];
    __shared__ int   s_stride;
    __shared__ float sm[WPB];
    __shared__ float ss[WPB];
    __shared__ __align__(16) float sacc[WPB][D_DIM];   // 16 KB merge slab
    __shared__ int   s_is_last;
    __shared__ float s_fin[SPLIT];
    __shared__ float s_inv;

    const int tid  = threadIdx.x;
    const int w    = tid >> 5;
    const int lane = tid & 31;
    const int g    = blockIdx.x / SPLIT;
    const int j    = blockIdx.x % SPLIT;

    // ---- batch dtype detection: nonzero odd word in [1,512) => int32 ----
    if (tid == 0) s_stride = 2;
    __syncthreads();
    {
        const int idx = 2 * tid + 1;
        if (idx < N && batch32[idx] != 0) s_stride = 1;
    }
    __syncthreads();
    const int bstride = s_stride;

    if (tid == 0)        sb[0] = lower_bound_batch(batch32, N, g, bstride);
    else if (tid == 32)  sb[1] = lower_bound_batch(batch32, N, g + 1, bstride);
    __syncthreads();
    const int start = sb[0], end = sb[1];

    const float bias = __ldg(bv);

    float4 w0, w1, w2, w3;
    if (VEC) {
        const float4* __restrict__ W4 = (const float4*)Wv;
        w0 = W4[lane]; w1 = W4[lane + 32]; w2 = W4[lane + 64]; w3 = W4[lane + 96];
    } else {
        const int c = lane * 4;
        w0 = make_float4(Wv[c+0],   Wv[c+1],   Wv[c+2],   Wv[c+3]);
        w1 = make_float4(Wv[c+128], Wv[c+129], Wv[c+130], Wv[c+131]);
        w2 = make_float4(Wv[c+256], Wv[c+257], Wv[c+258], Wv[c+259]);
        w3 = make_float4(Wv[c+384], Wv[c+385], Wv[c+386], Wv[c+387]);
    }

    float  m = -CUDART_INF_F, s = 0.f;
    float4 a0 = make_float4(0.f,0.f,0.f,0.f);
    float4 a1 = make_float4(0.f,0.f,0.f,0.f);
    float4 a2 = make_float4(0.f,0.f,0.f,0.f);
    float4 a3 = make_float4(0.f,0.f,0.f,0.f);

    int r = start + j * WPB + w;

    // ---- main loop: 2 rows per iteration (8 LDG.128 in flight) ----
    for (; r + RSTRIDE < end; r += 2 * RSTRIDE) {
        float4 u0,u1,u2,u3, v0,v1,v2,v3;
        if (VEC) {
            const float4* __restrict__ xr1 = (const float4*)(x + (size_t)r * D_DIM);
            const float4* __restrict__ xr2 = (const float4*)(x + (size_t)(r + RSTRIDE) * D_DIM);
            u0 = __ldcs(xr1 + lane);      u1 = __ldcs(xr1 + lane + 32);
            u2 = __ldcs(xr1 + lane + 64); u3 = __ldcs(xr1 + lane + 96);
            v0 = __ldcs(xr2 + lane);      v1 = __ldcs(xr2 + lane + 32);
            v2 = __ldcs(xr2 + lane + 64); v3 = __ldcs(xr2 + lane + 96);
        } else {
            const float* xr1 = x + (size_t)r * D_DIM + lane * 4;
            const float* xr2 = x + (size_t)(r + RSTRIDE) * D_DIM + lane * 4;
            u0 = make_float4(xr1[0],xr1[1],xr1[2],xr1[3]);
            u1 = make_float4(xr1[128],xr1[129],xr1[130],xr1[131]);
            u2 = make_float4(xr1[256],xr1[257],xr1[258],xr1[259]);
            u3 = make_float4(xr1[384],xr1[385],xr1[386],xr1[387]);
            v0 = make_float4(xr2[0],xr2[1],xr2[2],xr2[3]);
            v1 = make_float4(xr2[128],xr2[129],xr2[130],xr2[131]);
            v2 = make_float4(xr2[256],xr2[257],xr2[258],xr2[259]);
            v3 = make_float4(xr2[384],xr2[385],xr2[386],xr2[387]);
        }

        float d1, d2;
        ROW_DOT(d1, u0, u1, u2, u3, w0, w1, w2, w3);
        ROW_DOT(d2, v0, v1, v2, v3, w0, w1, w2, w3);
        #pragma unroll
        for (int off = 16; off; off >>= 1) {
            d1 += __shfl_xor_sync(0xffffffffu, d1, off);
            d2 += __shfl_xor_sync(0xffffffffu, d2, off);
        }
        const float g1 = d1 + bias;
        const float g2 = d2 + bias;
        const float mx = fmaxf(g1, g2);

        if (mx <= m) {
            // common: running max unchanged
            const float p1 = __expf(g1 - m);
            const float p2 = __expf(g2 - m);
            s += p1 + p2;
            AXPY2_4(a0, p1, u0, p2, v0);
            AXPY2_4(a1, p1, u1, p2, v1);
            AXPY2_4(a2, p1, u2, p2, v2);
            AXPY2_4(a3, p1, u3, p2, v3);
        } else {
            // new max (handles first iter via exp(-inf)=0)
            const float c  = __expf(m - mx);
            const float p1 = __expf(g1 - mx);
            const float p2 = __expf(g2 - mx);
            s = fmaf(s, c, p1 + p2);
            SCALE_AXPY2_4(a0, c, p1, u0, p2, v0);
            SCALE_AXPY2_4(a1, c, p1, u1, p2, v1);
            SCALE_AXPY2_4(a2, c, p1, u2, p2, v2);
            SCALE_AXPY2_4(a3, c, p1, u3, p2, v3);
            m = mx;
        }
    }

    // ---- tail: at most one leftover row ----
    if (r < end) {
        float4 u0,u1,u2,u3;
        if (VEC) {
            const float4* __restrict__ xr = (const float4*)(x + (size_t)r * D_DIM);
            u0 = __ldcs(xr + lane);      u1 = __ldcs(xr + lane + 32);
            u2 = __ldcs(xr + lane + 64); u3 = __ldcs(xr + lane + 96);
        } else {
            const float* xr = x + (size_t)r * D_DIM + lane * 4;
            u0 = make_float4(xr[0],xr[1],xr[2],xr[3]);
            u1 = make_float4(xr[128],xr[129],xr[130],xr[131]);
            u2 = make_float4(xr[256],xr[257],xr[258],xr[259]);
            u3 = make_float4(xr[384],xr[385],xr[386],xr[387]);
        }
        float d1;
        ROW_DOT(d1, u0, u1, u2, u3, w0, w1, w2, w3);
        #pragma unroll
        for (int off = 16; off; off >>= 1)
            d1 += __shfl_xor_sync(0xffffffffu, d1, off);
        const float gate = d1 + bias;
        if (gate <= m) {
            const float p = __expf(gate - m);
            s += p;
            AXPY4(a0, p, u0); AXPY4(a1, p, u1);
            AXPY4(a2, p, u2); AXPY4(a3, p, u3);
        } else {
            const float c = __expf(m - gate);
            s = fmaf(s, c, 1.0f);
            SCALE_AXPY4(a0, c, 1.0f, u0); SCALE_AXPY4(a1, c, 1.0f, u1);
            SCALE_AXPY4(a2, c, 1.0f, u2); SCALE_AXPY4(a3, c, 1.0f, u3);
            m = gate;
        }
    }

    // ---- merge 8 warps into one partial ----
    if (lane == 0) { sm[w] = m; ss[w] = s; }
    __syncthreads();

    float M = -CUDART_INF_F;
    #pragma unroll
    for (int k = 0; k < WPB; k++) M = fmaxf(M, sm[k]);

    const float f = (m == -CUDART_INF_F) ? 0.f : __expf(m - M);
    float4* slab = (float4*)&sacc[w][0];
    slab[lane]      = make_float4(a0.x*f, a0.y*f, a0.z*f, a0.w*f);
    slab[lane + 32] = make_float4(a1.x*f, a1.y*f, a1.z*f, a1.w*f);
    slab[lane + 64] = make_float4(a2.x*f, a2.y*f, a2.z*f, a2.w*f);
    slab[lane + 96] = make_float4(a3.x*f, a3.y*f, a3.z*f, a3.w*f);
    __syncthreads();

    float bs = 0.f;
    #pragma unroll
    for (int k = 0; k < WPB; k++) {
        const float mk = sm[k];
        const float fk = (mk == -CUDART_INF_F) ? 0.f : __expf(mk - M);
        bs = fmaf(fk, ss[k], bs);
    }

    float o0 = 0.f, o1 = 0.f;
    #pragma unroll
    for (int k = 0; k < WPB; k++) {
        o0 += sacc[k][tid];
        o1 += sacc[k][tid + 256];
    }
    const size_t pb = (size_t)blockIdx.x;
    g_part_acc[pb * D_DIM + tid]       = o0;
    g_part_acc[pb * D_DIM + tid + 256] = o1;
    if (tid == 0) { g_part_m[pb] = M; g_part_s[pb] = bs; }

    // ---- last-block-per-graph merges the SPLIT partials ----
    __threadfence();
    __syncthreads();
    if (tid == 0) {
        const int old = atomicAdd(&g_cnt[g], 1);
        s_is_last = (old == SPLIT - 1);
    }
    __syncthreads();
    if (!s_is_last) return;

    __threadfence();   // order partial reads after observing all arrivals

    if (tid < 32) {
        float mm  = (tid < SPLIT) ? g_part_m[g * SPLIT + tid] : -CUDART_INF_F;
        float svl = (tid < SPLIT) ? g_part_s[g * SPLIT + tid] : 0.f;
        float Mg = mm;
        #pragma unroll
        for (int off = 16; off; off >>= 1)
            Mg = fmaxf(Mg, __shfl_xor_sync(0xffffffffu, Mg, off));
        const float fj = (mm == -CUDART_INF_F) ? 0.f : __expf(mm - Mg);
        float dj = fj * svl;
        #pragma unroll
        for (int off = 16; off; off >>= 1)
            dj += __shfl_xor_sync(0xffffffffu, dj, off);
        if (tid < SPLIT) s_fin[tid] = fj;
        if (tid == 0)    s_inv = (dj > 0.f) ? (1.f / dj) : 0.f;   // empty graph -> zeros
    }
    __syncthreads();

    const float f0 = s_fin[0], f1 = s_fin[1], f2 = s_fin[2], f3 = s_fin[3];
    const float inv = s_inv;
    const float* __restrict__ P = g_part_acc + (size_t)g * SPLIT * D_DIM;

    #pragma unroll
    for (int c = tid; c < D_DIM; c += T_P1) {
        const float v = f0 * P[c]
                      + f1 * P[c + D_DIM]
                      + f2 * P[c + 2 * D_DIM]
                      + f3 * P[c + 3 * D_DIM];
        out[(size_t)g * D_DIM + c] = v * inv;
    }

    if (tid == 0) g_cnt[g] = 0;   // reset for graph replay determinism
}

extern "C" void kernel_launch(void* const* d_in, const int* in_sizes, int n_in,
                              void* d_out, int out_size)
{
    const float* x       = (const float*)d_in[0];
    const float* W       = (const float*)d_in[1];
    const float* b       = (const float*)d_in[2];
    const int*   batch32 = (const int*)d_in[3];   // int32 or int64 (device-detected)
    const int N = in_sizes[3];
    (void)n_in; (void)out_size;

    const bool vec_in = ((((uintptr_t)x) | ((uintptr_t)W)) & 15u) == 0;

    if (vec_in)
        gap_fused<true><<<G_NUM * SPLIT, T_P1>>>(x, W, b, batch32, N, (float*)d_out);
    else
        gap_fused<false><<<G_NUM * SPLIT, T_P1>>>(x, W, b, batch32, N, (float*)d_out);
}